// round 15
// baseline (speedup 1.0000x reference)
#include <cuda_runtime.h>

// upfirdn2d(up=2, down=1, pad=5), 12x12 separable K = h h^T, via fma.rn.f32x2.
// R13 skeleton (best: 110.6us): 256 threads, parity-pair outputs, broadcast-
// input FFMA2, sliding register windows, idx-based loads, st.global.cs with
// immediate-offset addressing.
// R14: TILE_W 128->120 -> smem 27.7KB + __launch_bounds__(256,8) -> 8 blocks/SM
// (was 7): one more independent barrier-domain per SM for DRAM phase overlap.

#define IMG_H 256
#define IMG_W 256
#define OUT_H 511
#define OUT_W 511
#define TILE_W 120
#define TILE_H 64
#define IN_W  65      // input cols per 120-wide output tile
#define IN_H  37      // input rows per 64-tall output tile
#define SPITCH 65     // 65 mod 32 = 1 -> conflict-free s_in reads
#define NP    60      // output column pairs per tile
#define TP2   61      // float2 pitch for tmp rows (odd -> conflict-free STS.64)
#define NTHR  256

__device__ __forceinline__ float2 ffma2(float2 a, float2 b, float2 c) {
    float2 d;
    asm("fma.rn.f32x2 %0, %1, %2, %3;"
        : "=l"(*reinterpret_cast<unsigned long long*>(&d))
        : "l"(*reinterpret_cast<unsigned long long*>(&a)),
          "l"(*reinterpret_cast<unsigned long long*>(&b)),
          "l"(*reinterpret_cast<unsigned long long*>(&c)));
    return d;
}

__device__ __forceinline__ float2 fmul2(float2 a, float2 b) {
    float2 d;
    asm("mul.rn.f32x2 %0, %1, %2;"
        : "=l"(*reinterpret_cast<unsigned long long*>(&d))
        : "l"(*reinterpret_cast<unsigned long long*>(&a)),
          "l"(*reinterpret_cast<unsigned long long*>(&b)));
    return d;
}

__device__ __forceinline__ float2 bcast(float w) { return make_float2(w, w); }

__device__ __forceinline__ void stcs(float* p, float v) {
    asm volatile("st.global.cs.f32 [%0], %1;" :: "l"(p), "f"(v));
}

__global__ __launch_bounds__(NTHR, 8)
void lpf_up2_kernel(const float* __restrict__ x,
                    const float* __restrict__ K,
                    float* __restrict__ out) {
    __shared__ float  s_in[IN_H * SPITCH];   // 37 x 65 input tile (9.6 KB)
    __shared__ float2 s_tmp[IN_H * TP2];     // horiz result: 37 x 60 pairs (18.1 KB)
    __shared__ float2 s_c[6];                // (h_even_tap[t], h_odd_tap[t])

    const int tid = threadIdx.x;
    const int img = blockIdx.z;
    const int ox0 = blockIdx.x * TILE_W;     // even
    const int oy0 = blockIdx.y * TILE_H;     // even
    const int mx0 = (ox0 >> 1) - 2;
    const int my0 = (oy0 >> 1) - 2;

    // Recover separable h from K row 5: h[j] = K[5][j] / sqrt(K[5][5]).
    // Sign ambiguity cancels (all taps are h*h products).
    if (tid < 6) {
        float s = rsqrtf(K[5 * 12 + 5]);
        s_c[tid] = make_float2(K[5 * 12 + (10 - 2 * tid)] * s,
                               K[5 * 12 + (11 - 2 * tid)] * s);
    }

    // ---- Load input tile (independent iterations -> high MLP) ----
    const float* __restrict__ xin = x + (size_t)img * (IMG_H * IMG_W);
    #pragma unroll
    for (int idx = tid; idx < IN_H * IN_W; idx += NTHR) {
        int r = idx / IN_W;
        int c = idx - r * IN_W;
        int gy = my0 + r;
        int gx = mx0 + c;
        float v = 0.0f;
        if ((unsigned)gy < IMG_H && (unsigned)gx < IMG_W)
            v = xin[gy * IMG_W + gx];
        s_in[r * SPITCH + c] = v;
    }
    __syncthreads();

    const float2 c0 = s_c[0], c1 = s_c[1], c2 = s_c[2],
                 c3 = s_c[3], c4 = s_c[4], c5 = s_c[5];

    // ---- Horizontal pass: tmp[r][pair k] = sum_t c[t]*s_in[r][k+t] ----
    // 37 rows x 15 groups of 4 pairs = 555 tasks; threads 0..42 take 3rd slot.
    #pragma unroll
    for (int tt = 0; tt < 3; tt++) {
        int t = tid + NTHR * tt;
        if (t < IN_H * 15) {
            int kg = t / IN_H;            // 0..14
            int r  = t - kg * IN_H;       // 0..36
            int k0 = kg * 4;
            const float* row = s_in + r * SPITCH + k0;
            float2* trow = s_tmp + r * TP2 + k0;
            float2 p0 = bcast(row[0]), p1 = bcast(row[1]),
                   p2 = bcast(row[2]), p3 = bcast(row[3]),
                   p4 = bcast(row[4]), p5 = bcast(row[5]);
            #pragma unroll
            for (int j = 0; j < 4; j++) {
                float2 acc = fmul2(p0, c0);
                acc = ffma2(p1, c1, acc);
                acc = ffma2(p2, c2, acc);
                acc = ffma2(p3, c3, acc);
                acc = ffma2(p4, c4, acc);
                acc = ffma2(p5, c5, acc);
                trow[j] = acc;
                p0 = p1; p1 = p2; p2 = p3; p3 = p4; p4 = p5;
                if (j < 3) p5 = bcast(row[j + 6]);   // max col 56+3+5 = 64
            }
        }
    }
    __syncthreads();

    // ---- Vertical pass: out rows (2J, 2J+1) = sum_t c[t]*tmp[J+t][ox] ----
    // 120 columns x 2 groups of 16 row-pairs = 240 active threads.
    if (tid < 2 * TILE_W) {
        const int j0 = (tid >= TILE_W) ? 16 : 0;
        const int ox = tid - ((tid >= TILE_W) ? TILE_W : 0);
        const float* tcol =
            reinterpret_cast<const float*>(s_tmp) + j0 * (TP2 * 2) + ox;
        float2 v0 = bcast(tcol[0 * (TP2 * 2)]);
        float2 v1 = bcast(tcol[1 * (TP2 * 2)]);
        float2 v2 = bcast(tcol[2 * (TP2 * 2)]);
        float2 v3 = bcast(tcol[3 * (TP2 * 2)]);
        float2 v4 = bcast(tcol[4 * (TP2 * 2)]);
        float2 v5 = bcast(tcol[5 * (TP2 * 2)]);

        const int  gox = ox0 + ox;
        const bool xok = (gox < OUT_W);
        // Base pointer; per-j store offsets are compile-time immediates.
        float* __restrict__ p =
            out + (size_t)img * ((size_t)OUT_H * OUT_W) +
            (size_t)(oy0 + 2 * j0) * OUT_W + gox;
        // Only oy0=448, j0=16, j=15 would write row 511: skip it.
        const bool lastgrp = (oy0 + 2 * j0 == 480);

        #pragma unroll
        for (int j = 0; j < 16; j++) {
            float2 acc = fmul2(v0, c0);
            acc = ffma2(v1, c1, acc);
            acc = ffma2(v2, c2, acc);
            acc = ffma2(v3, c3, acc);
            acc = ffma2(v4, c4, acc);
            acc = ffma2(v5, c5, acc);
            if (xok) {
                stcs(p + (size_t)(2 * j) * OUT_W, acc.x);   // even row <= 510
                if (!lastgrp || j < 15)                      // skip row 511
                    stcs(p + (size_t)(2 * j + 1) * OUT_W, acc.y);
            }
            v0 = v1; v1 = v2; v2 = v3; v3 = v4; v4 = v5;
            if (j < 15) v5 = bcast(tcol[(j + 6) * (TP2 * 2)]); // row <= 36
        }
    }
}

extern "C" void kernel_launch(void* const* d_in, const int* in_sizes, int n_in,
                              void* d_out, int out_size) {
    const float* x = (const float*)d_in[0];   // [8,64,256,256] f32
    const float* K = (const float*)d_in[1];   // [12,12] f32
    float* out = (float*)d_out;               // [8,64,511,511] f32

    int imgs = in_sizes[0] / (IMG_H * IMG_W); // 512
    dim3 grid((OUT_W + TILE_W - 1) / TILE_W,  // 5
              (OUT_H + TILE_H - 1) / TILE_H,  // 8
              imgs);                          // 512
    lpf_up2_kernel<<<grid, NTHR>>>(x, K, out);
}

// round 16
// speedup vs baseline: 1.1208x; 1.1208x over previous
#include <cuda_runtime.h>

// upfirdn2d(up=2, down=1, pad=5), 12x12 separable K = h h^T, via fma.rn.f32x2.
// R15: FUSED separable filter. Each thread owns one output column and slides a
// private 6-deep register window of horizontal results down the tile:
//   step j: new_w = sum_s h_par[s]*s_in[j+5][kx+s]   (6 scalar FMA, 6 LDS)
//           out rows (2j,2j+1) = sum_t (he,ho)[t]*bcast(w[t])  (6 FFMA2)
// -> no s_tmp, ONE barrier, stores interleaved with compute (steady DRAM
// stream), smem ~19.6KB -> 256-wide tile (x-halo 1.039).

#define IMG_H 256
#define IMG_W 256
#define OUT_H 511
#define OUT_W 511
#define TILE_W 256
#define TILE_H 64
#define IN_W  133     // input cols per 256-wide output tile
#define IN_H  37      // input rows per 64-tall output tile
#define SPITCH 133    // odd -> conflict-free
#define NTHR  256

__device__ __forceinline__ float2 ffma2(float2 a, float2 b, float2 c) {
    float2 d;
    asm("fma.rn.f32x2 %0, %1, %2, %3;"
        : "=l"(*reinterpret_cast<unsigned long long*>(&d))
        : "l"(*reinterpret_cast<unsigned long long*>(&a)),
          "l"(*reinterpret_cast<unsigned long long*>(&b)),
          "l"(*reinterpret_cast<unsigned long long*>(&c)));
    return d;
}

__device__ __forceinline__ float2 fmul2(float2 a, float2 b) {
    float2 d;
    asm("mul.rn.f32x2 %0, %1, %2;"
        : "=l"(*reinterpret_cast<unsigned long long*>(&d))
        : "l"(*reinterpret_cast<unsigned long long*>(&a)),
          "l"(*reinterpret_cast<unsigned long long*>(&b)));
    return d;
}

__device__ __forceinline__ float2 bcast(float w) { return make_float2(w, w); }

__device__ __forceinline__ void stcs(float* p, float v) {
    asm volatile("st.global.cs.f32 [%0], %1;" :: "l"(p), "f"(v));
}

__global__ __launch_bounds__(NTHR)
void lpf_up2_kernel(const float* __restrict__ x,
                    const float* __restrict__ K,
                    float* __restrict__ out) {
    __shared__ float  s_in[IN_H * SPITCH];   // 37 x 133 input tile (19.2 KB)
    __shared__ float2 s_c[6];                // (h_even_tap[t], h_odd_tap[t])

    const int tid = threadIdx.x;
    const int img = blockIdx.z;
    const int ox0 = blockIdx.x * TILE_W;     // even
    const int oy0 = blockIdx.y * TILE_H;     // even
    const int mx0 = (ox0 >> 1) - 2;
    const int my0 = (oy0 >> 1) - 2;

    // Recover separable h from K row 5: h[j] = K[5][j] / sqrt(K[5][5]).
    // Sign ambiguity cancels (all taps are h*h products).
    if (tid < 6) {
        float s = rsqrtf(K[5 * 12 + 5]);
        s_c[tid] = make_float2(K[5 * 12 + (10 - 2 * tid)] * s,
                               K[5 * 12 + (11 - 2 * tid)] * s);
    }

    // ---- Load input tile (independent iterations -> high MLP) ----
    const float* __restrict__ xin = x + (size_t)img * (IMG_H * IMG_W);
    #pragma unroll
    for (int idx = tid; idx < IN_H * IN_W; idx += NTHR) {
        int r = idx / IN_W;
        int c = idx - r * IN_W;
        int gy = my0 + r;
        int gx = mx0 + c;
        float v = 0.0f;
        if ((unsigned)gy < IMG_H && (unsigned)gx < IMG_W)
            v = xin[gy * IMG_W + gx];
        s_in[r * SPITCH + c] = v;
    }
    __syncthreads();

    // Vertical coefficient pairs (he[t], ho[t]) -- shared with horizontal.
    const float2 c0 = s_c[0], c1 = s_c[1], c2 = s_c[2],
                 c3 = s_c[3], c4 = s_c[4], c5 = s_c[5];

    // Horizontal scalar taps for THIS column's parity.
    const int col = tid;                 // output column within tile, 0..255
    const int par = col & 1;
    const float h0 = par ? c0.y : c0.x;
    const float h1 = par ? c1.y : c1.x;
    const float h2 = par ? c2.y : c2.x;
    const float h3 = par ? c3.y : c3.x;
    const float h4 = par ? c4.y : c4.x;
    const float h5 = par ? c5.y : c5.x;

    // Horizontal window base column in s_in: kx..kx+5 (kx <= 127, +5 <= 132).
    const float* rowp = s_in + (col >> 1);

    // tmp(r) = sum_s h[s] * s_in[r][kx+s]
    #define TMPVAL(R) (h0 * rowp[(R) * SPITCH + 0] + h1 * rowp[(R) * SPITCH + 1] \
                     + h2 * rowp[(R) * SPITCH + 2] + h3 * rowp[(R) * SPITCH + 3] \
                     + h4 * rowp[(R) * SPITCH + 4] + h5 * rowp[(R) * SPITCH + 5])

    // Init 6-deep broadcast window of horizontal results (rows 0..5).
    float2 w0 = bcast(TMPVAL(0));
    float2 w1 = bcast(TMPVAL(1));
    float2 w2 = bcast(TMPVAL(2));
    float2 w3 = bcast(TMPVAL(3));
    float2 w4 = bcast(TMPVAL(4));
    float2 w5 = bcast(TMPVAL(5));

    const int  gox = ox0 + col;
    const bool xok = (gox < OUT_W);
    float* __restrict__ p =
        out + (size_t)img * ((size_t)OUT_H * OUT_W) + (size_t)oy0 * OUT_W + gox;
    // Only oy0=448, j=31 would write odd row 511: skip it.
    const bool lastblk = (oy0 == 448);

    // ---- Fused sweep: 32 output row-pairs ----
    #pragma unroll
    for (int j = 0; j < 32; j++) {
        float2 acc = fmul2(w0, c0);      // (even-row, odd-row) outputs
        acc = ffma2(w1, c1, acc);
        acc = ffma2(w2, c2, acc);
        acc = ffma2(w3, c3, acc);
        acc = ffma2(w4, c4, acc);
        acc = ffma2(w5, c5, acc);
        if (xok) {
            stcs(p + (size_t)(2 * j) * OUT_W, acc.x);       // row <= 510
            if (!lastblk || j < 31)                          // skip row 511
                stcs(p + (size_t)(2 * j + 1) * OUT_W, acc.y);
        }
        w0 = w1; w1 = w2; w2 = w3; w3 = w4; w4 = w5;
        if (j < 31) w5 = bcast(TMPVAL(j + 6));               // max row 36
    }
    #undef TMPVAL
}

extern "C" void kernel_launch(void* const* d_in, const int* in_sizes, int n_in,
                              void* d_out, int out_size) {
    const float* x = (const float*)d_in[0];   // [8,64,256,256] f32
    const float* K = (const float*)d_in[1];   // [12,12] f32
    float* out = (float*)d_out;               // [8,64,511,511] f32

    int imgs = in_sizes[0] / (IMG_H * IMG_W); // 512
    dim3 grid((OUT_W + TILE_W - 1) / TILE_W,  // 2
              (OUT_H + TILE_H - 1) / TILE_H,  // 8
              imgs);                          // 512
    lpf_up2_kernel<<<grid, NTHR>>>(x, K, out);
}